// round 7
// baseline (speedup 1.0000x reference)
#include <cuda_runtime.h>
#include <cuda_fp16.h>
#include <cstdint>
#include <math.h>

#define B_ 4
#define H_ 16
#define S_ 2048
#define D_ 1024
#define BH 64
#define dh 64
#define NEGV (-1000000.0f)

// ============================ device scratch ============================
__device__ __half g_Yhi[(size_t)BH * S_ * dh];
__device__ __half g_Ylo[(size_t)BH * S_ * dh];
__device__ __half g_XhiT[(size_t)BH * dh * S_];   // [bh][c][s]

// ============================ PTX helpers ============================
__device__ __forceinline__ uint32_t smem_u32(const void* p) {
    uint32_t a;
    asm("{ .reg .u64 t; cvta.to.shared.u64 t, %1; cvt.u32.u64 %0, t; }" : "=r"(a) : "l"(p));
    return a;
}
#define LDSM_X4(r0, r1, r2, r3, addr) \
    asm volatile("ldmatrix.sync.aligned.m8n8.x4.shared.b16 {%0,%1,%2,%3}, [%4];" \
        : "=r"(r0), "=r"(r1), "=r"(r2), "=r"(r3) : "r"(addr))
#define CP_ASYNC16(dst, src) \
    asm volatile("cp.async.cg.shared.global [%0], [%1], 16;" :: "r"(dst), "l"(src))
#define CP_COMMIT() asm volatile("cp.async.commit_group;")
#define CP_WAIT0()  asm volatile("cp.async.wait_group 0;")

__device__ __forceinline__ void mma16816(float d[4], const uint32_t a[4], const uint32_t b[2]) {
    asm volatile(
        "mma.sync.aligned.m16n8k16.row.col.f32.f16.f16.f32 "
        "{%0,%1,%2,%3}, {%4,%5,%6,%7}, {%8,%9}, {%0,%1,%2,%3};"
        : "+f"(d[0]), "+f"(d[1]), "+f"(d[2]), "+f"(d[3])
        : "r"(a[0]), "r"(a[1]), "r"(a[2]), "r"(a[3]), "r"(b[0]), "r"(b[1]));
}
__device__ __forceinline__ uint32_t packh(float a, float b) {
    __half2 h = __floats2half2_rn(a, b);
    return *(uint32_t*)&h;
}

// ============================ fused prep (MMA-based, unchanged) ============================
#define PROWB 144
#define PSXL 18432
#define PSWH 36864
#define PSWL 46080
#define PREP_SMEM 55296

__global__ void __launch_bounds__(256, 1) prep_mma(const float* __restrict__ x,
                                                   const float* __restrict__ W,
                                                   const float* __restrict__ bias) {
    extern __shared__ char smem[];
    uint32_t sb = smem_u32(smem);
    int tid = threadIdx.x;
    int w = tid >> 5, l = tid & 31;
    int bh = blockIdx.x >> 4;
    int s0 = (blockIdx.x & 15) * 128;
    int b = bh >> 4, h = bh & 15;

    #pragma unroll
    for (int t = 0; t < 16; t++) {
        int idx = t * 256 + tid;
        int i = idx >> 6, j = idx & 63;
        float v = W[idx];
        __half hi = __float2half_rn(v);
        *(__half*)(smem + PSWH + j * PROWB + i * 2) = hi;
        *(__half*)(smem + PSWL + j * PROWB + i * 2) = __float2half_rn(v - __half2float(hi));
    }

    #pragma unroll
    for (int t = 0; t < 8; t++) {
        int idx = t * 256 + tid;
        int row = idx >> 4, q = idx & 15;
        float4 v = *(const float4*)(x + (size_t)(b * S_ + s0 + row) * D_ + h * 64 + q * 4);
        __half h0 = __float2half_rn(v.x), h1 = __float2half_rn(v.y);
        __half h2 = __float2half_rn(v.z), h3 = __float2half_rn(v.w);
        uint2 hiw = make_uint2(packh(v.x, v.y), packh(v.z, v.w));
        uint2 low = make_uint2(packh(v.x - __half2float(h0), v.y - __half2float(h1)),
                               packh(v.z - __half2float(h2), v.w - __half2float(h3)));
        *(uint2*)(smem + row * PROWB + q * 8) = hiw;
        *(uint2*)(smem + PSXL + row * PROWB + q * 8) = low;
    }
    __syncthreads();

    #pragma unroll
    for (int t = 0; t < 4; t++) {
        int u = t * 256 + tid;
        int c = (u >> 4) & 63;
        int g8 = u & 15;
        uint32_t base = (uint32_t)c * 2;
        uint32_t pk[4];
        #pragma unroll
        for (int p = 0; p < 4; p++) {
            uint16_t a0 = *(const uint16_t*)(smem + base + (g8 * 8 + 2 * p) * PROWB);
            uint16_t a1 = *(const uint16_t*)(smem + base + (g8 * 8 + 2 * p + 1) * PROWB);
            pk[p] = (uint32_t)a0 | ((uint32_t)a1 << 16);
        }
        __half* dst = g_XhiT + ((size_t)bh * 64 + c) * S_ + s0 + g8 * 8;
        *(uint4*)dst = *(uint4*)pk;
    }

    uint32_t ahi[4][4], alo[4][4];
    #pragma unroll
    for (int j = 0; j < 4; j++) {
        uint32_t ad = sb + (uint32_t)(w * 16 + (l & 15)) * PROWB +
                      (uint32_t)(((l >> 4) * 8 + 16 * j) * 2);
        LDSM_X4(ahi[j][0], ahi[j][1], ahi[j][2], ahi[j][3], ad);
        LDSM_X4(alo[j][0], alo[j][1], alo[j][2], alo[j][3], ad + PSXL);
    }

    int R0 = w * 16 + (l >> 2);
    #pragma unroll
    for (int t2 = 0; t2 < 8; t2++) {
        uint32_t b0 = sb + PSWH + (uint32_t)(t2 * 8 + (l & 7)) * PROWB +
                      (uint32_t)(((l >> 3) * 8) * 2);
        uint32_t bh0, bh1, bh2, bh3, bh4, bh5, bh6, bh7;
        uint32_t bl0, bl1, bl2, bl3, bl4, bl5, bl6, bl7;
        LDSM_X4(bh0, bh1, bh2, bh3, b0);
        LDSM_X4(bh4, bh5, bh6, bh7, b0 + 64u);
        LDSM_X4(bl0, bl1, bl2, bl3, b0 + (PSWL - PSWH));
        LDSM_X4(bl4, bl5, bl6, bl7, b0 + (PSWL - PSWH) + 64u);
        uint32_t bhv[8] = {bh0, bh1, bh2, bh3, bh4, bh5, bh6, bh7};
        uint32_t blv[8] = {bl0, bl1, bl2, bl3, bl4, bl5, bl6, bl7};

        float y[4] = {0.0f, 0.0f, 0.0f, 0.0f};
        #pragma unroll
        for (int j = 0; j < 4; j++) {
            mma16816(y, ahi[j], &bhv[2 * j]);
            mma16816(y, alo[j], &bhv[2 * j]);
            mma16816(y, ahi[j], &blv[2 * j]);
        }

        int c = t2 * 8 + (l & 3) * 2;
        float b0f = bias[c], b1f = bias[c + 1];
        y[0] += b0f; y[1] += b1f; y[2] += b0f; y[3] += b1f;

        __half h0 = __float2half_rn(y[0]), h1 = __float2half_rn(y[1]);
        __half h2 = __float2half_rn(y[2]), h3 = __float2half_rn(y[3]);
        size_t o0 = ((size_t)bh * S_ + s0 + R0) * 64 + c;
        size_t o1 = ((size_t)bh * S_ + s0 + R0 + 8) * 64 + c;
        *(uint32_t*)(g_Yhi + o0) = packh(y[0], y[1]);
        *(uint32_t*)(g_Yhi + o1) = packh(y[2], y[3]);
        *(uint32_t*)(g_Ylo + o0) = packh(y[0] - __half2float(h0), y[1] - __half2float(h1));
        *(uint32_t*)(g_Ylo + o1) = packh(y[2] - __half2float(h2), y[3] - __half2float(h3));
    }
}

// ============================ attention kernel ============================
// 128-thread CTAs over 64-row q-tiles; 3 CTAs/SM for cross-CTA tensor overlap.
// Stage layout (27648 B): YKH(0) YKL(9216) XTH(18432). Two stages.
// Yq (hi at sb+0, lo at sb+9216) is transient; frags extracted before prefetch.
#define STG 27648
#define ROWB 144

__device__ __forceinline__ void load_stage(uint32_t base, int bh, int kt, int tid) {
    #pragma unroll
    for (int t = 0; t < 12; t++) {
        int tile = t >> 2;                      // 0: Yhi, 1: Ylo, 2: XhiT
        int idx  = ((t & 3) << 7) + tid;        // 0..511
        int n = idx >> 3, o = idx & 7;
        uint32_t dst = base + (uint32_t)tile * 9216u + (uint32_t)n * ROWB + (uint32_t)o * 16u;
        const __half* src;
        if (tile == 0)      src = g_Yhi  + ((size_t)bh * S_ + kt * 64 + n) * 64 + o * 8;
        else if (tile == 1) src = g_Ylo  + ((size_t)bh * S_ + kt * 64 + n) * 64 + o * 8;
        else                src = g_XhiT + ((size_t)bh * 64 + n) * S_ + kt * 64 + o * 8;
        CP_ASYNC16(dst, src);
    }
    CP_COMMIT();
}

__global__ void __launch_bounds__(128, 3) attn_mma(const int* __restrict__ mask,
                                                   float* __restrict__ out) {
    extern __shared__ char smem[];
    uint32_t sb = smem_u32(smem);
    int tid = threadIdx.x;
    int w = tid >> 5, l = tid & 31;
    int bh = blockIdx.y, b = bh >> 4;
    int q0 = blockIdx.x * 64;

    // ---- Yq (hi/lo, 64 rows) into [0, 18432) via cp.async ----
    #pragma unroll
    for (int t = 0; t < 8; t++) {
        int sel = t >> 2;
        int ii  = ((t & 3) << 7) + tid;         // 0..511
        int row = ii >> 3, o = ii & 7;
        uint32_t dst = sb + (uint32_t)sel * 9216u + (uint32_t)row * ROWB + (uint32_t)o * 16u;
        const __half* src = (sel ? g_Ylo : g_Yhi) + ((size_t)bh * S_ + q0 + row) * 64 + o * 8;
        CP_ASYNC16(dst, src);
    }
    CP_COMMIT();
    CP_WAIT0();
    __syncthreads();

    // ---- extract Yq A-fragments ----
    uint32_t ahi[4][4], alo[4][4];
    #pragma unroll
    for (int j = 0; j < 4; j++) {
        uint32_t ad = sb + (uint32_t)(w * 16 + (l & 15)) * ROWB +
                      (uint32_t)(((l >> 4) * 8 + 16 * j) * 2);
        LDSM_X4(ahi[j][0], ahi[j][1], ahi[j][2], ahi[j][3], ad);
        LDSM_X4(alo[j][0], alo[j][1], alo[j][2], alo[j][3], ad + 9216u);
    }
    __syncthreads();   // all warps done reading Yq before prefetch overwrites

    // ---- prefetch ktile 0 into stage1 ----
    load_stage(sb + STG, bh, 0, tid);
    CP_WAIT0();
    __syncthreads();

    int R0 = q0 + w * 16 + (l >> 2);
    float negv0 = (1.0f - (float)mask[(size_t)b * S_ + R0]) * NEGV;
    float negv1 = (1.0f - (float)mask[(size_t)b * S_ + R0 + 8]) * NEGV;

    float pv[8][4];
    #pragma unroll
    for (int t = 0; t < 8; t++)
        #pragma unroll
        for (int q = 0; q < 4; q++) pv[t][q] = 0.0f;
    float l0 = 0.0f, l1 = 0.0f;

    uint32_t pAhi[4][4];

    for (int kt = 0; kt < 32; kt++) {
        uint32_t cur = sb + (uint32_t)((kt + 1) & 1) * STG;
        if (kt < 31) load_stage(sb + (uint32_t)(kt & 1) * STG, bh, kt + 1, tid);

        // ---- scores (3-term) + softmax + P-pack ----
        #pragma unroll
        for (int t = 0; t < 8; t++) {
            uint32_t b0 = cur + (uint32_t)(t * 8 + (l & 7)) * ROWB + (uint32_t)(((l >> 3) * 8) * 2);
            uint32_t bh0, bh1, bh2, bh3, bh4, bh5, bh6, bh7;
            uint32_t bl0, bl1, bl2, bl3, bl4, bl5, bl6, bl7;
            LDSM_X4(bh0, bh1, bh2, bh3, b0);
            LDSM_X4(bh4, bh5, bh6, bh7, b0 + 64u);
            LDSM_X4(bl0, bl1, bl2, bl3, b0 + 9216u);
            LDSM_X4(bl4, bl5, bl6, bl7, b0 + 9216u + 64u);
            uint32_t bhv[8] = {bh0, bh1, bh2, bh3, bh4, bh5, bh6, bh7};
            uint32_t blv[8] = {bl0, bl1, bl2, bl3, bl4, bl5, bl6, bl7};

            float s[4] = {0.0f, 0.0f, 0.0f, 0.0f};
            #pragma unroll
            for (int j = 0; j < 4; j++) {
                mma16816(s, ahi[j], &bhv[2 * j]);
                mma16816(s, alo[j], &bhv[2 * j]);
                mma16816(s, ahi[j], &blv[2 * j]);
            }

            float lg0 = __fadd_rn(__fmul_rn(s[0], 0.015625f), negv0);
            float lg1 = __fadd_rn(__fmul_rn(s[1], 0.015625f), negv0);
            float lg2 = __fadd_rn(__fmul_rn(s[2], 0.015625f), negv1);
            float lg3 = __fadd_rn(__fmul_rn(s[3], 0.015625f), negv1);
            float p0 = __expf(lg0 - negv0);
            float p1 = __expf(lg1 - negv0);
            float p2 = __expf(lg2 - negv1);
            float p3 = __expf(lg3 - negv1);
            l0 += p0 + p1;
            l1 += p2 + p3;

            pAhi[t >> 1][(t & 1) * 2 + 0] = packh(p0, p1);
            pAhi[t >> 1][(t & 1) * 2 + 1] = packh(p2, p3);
        }

        // ---- PV (1-term): pv += P_hi . X_hi ----
        #pragma unroll
        for (int t2 = 0; t2 < 8; t2++) {
            uint32_t b0 = cur + 18432u + (uint32_t)(t2 * 8 + (l & 7)) * ROWB +
                          (uint32_t)(((l >> 3) * 8) * 2);
            uint32_t bh0, bh1, bh2, bh3, bh4, bh5, bh6, bh7;
            LDSM_X4(bh0, bh1, bh2, bh3, b0);
            LDSM_X4(bh4, bh5, bh6, bh7, b0 + 64u);
            uint32_t bhv[8] = {bh0, bh1, bh2, bh3, bh4, bh5, bh6, bh7};
            #pragma unroll
            for (int j = 0; j < 4; j++)
                mma16816(pv[t2], pAhi[j], &bhv[2 * j]);
        }

        CP_WAIT0();
        __syncthreads();
    }

    // ---- epilogue ----
    l0 += __shfl_xor_sync(0xffffffffu, l0, 1);
    l0 += __shfl_xor_sync(0xffffffffu, l0, 2);
    l1 += __shfl_xor_sync(0xffffffffu, l1, 1);
    l1 += __shfl_xor_sync(0xffffffffu, l1, 2);
    float i0 = 1.0f / l0, i1 = 1.0f / l1;

    #pragma unroll
    for (int t2 = 0; t2 < 8; t2++) {
        int c = t2 * 8 + (l & 3) * 2;
        float2 v0 = make_float2(pv[t2][0] * i0, pv[t2][1] * i0);
        float2 v1 = make_float2(pv[t2][2] * i1, pv[t2][3] * i1);
        *(float2*)(out + ((size_t)bh * S_ + R0) * 64 + c)     = v0;
        *(float2*)(out + ((size_t)bh * S_ + R0 + 8) * 64 + c) = v1;
    }
}

// ============================ launch ============================
extern "C" void kernel_launch(void* const* d_in, const int* in_sizes, int n_in,
                              void* d_out, int out_size) {
    const float* x    = (const float*)d_in[0];
    const int*   mask = (const int*)d_in[1];
    const float* W    = (const float*)d_in[2];
    const float* bias = (const float*)d_in[3];
    float* out = (float*)d_out;

    cudaFuncSetAttribute(prep_mma, cudaFuncAttributeMaxDynamicSharedMemorySize, PREP_SMEM);
    prep_mma<<<BH * 16, 256, PREP_SMEM>>>(x, W, bias);

    cudaFuncSetAttribute(attn_mma, cudaFuncAttributeMaxDynamicSharedMemorySize, 2 * STG);
    dim3 grid(S_ / 64, BH);
    attn_mma<<<grid, 128, 2 * STG>>>(mask, out);
}

// round 8
// speedup vs baseline: 1.0381x; 1.0381x over previous
#include <cuda_runtime.h>
#include <cuda_fp16.h>
#include <cstdint>
#include <math.h>

#define B_ 4
#define H_ 16
#define S_ 2048
#define D_ 1024
#define BH 64
#define dh 64
#define NEGV (-1000000.0f)

// ============================ device scratch ============================
__device__ __half g_Yhi[(size_t)BH * S_ * dh];
__device__ __half g_Ylo[(size_t)BH * S_ * dh];
__device__ __half g_XhiT[(size_t)BH * dh * S_];   // [bh][c][s]

// ============================ PTX helpers ============================
__device__ __forceinline__ uint32_t smem_u32(const void* p) {
    uint32_t a;
    asm("{ .reg .u64 t; cvta.to.shared.u64 t, %1; cvt.u32.u64 %0, t; }" : "=r"(a) : "l"(p));
    return a;
}
#define LDSM_X4(r0, r1, r2, r3, addr) \
    asm volatile("ldmatrix.sync.aligned.m8n8.x4.shared.b16 {%0,%1,%2,%3}, [%4];" \
        : "=r"(r0), "=r"(r1), "=r"(r2), "=r"(r3) : "r"(addr))
#define CP_ASYNC16(dst, src) \
    asm volatile("cp.async.cg.shared.global [%0], [%1], 16;" :: "r"(dst), "l"(src))
#define CP_COMMIT() asm volatile("cp.async.commit_group;")
#define CP_WAIT0()  asm volatile("cp.async.wait_group 0;")

__device__ __forceinline__ void mma16816(float d[4], const uint32_t a[4], const uint32_t b[2]) {
    asm volatile(
        "mma.sync.aligned.m16n8k16.row.col.f32.f16.f16.f32 "
        "{%0,%1,%2,%3}, {%4,%5,%6,%7}, {%8,%9}, {%0,%1,%2,%3};"
        : "+f"(d[0]), "+f"(d[1]), "+f"(d[2]), "+f"(d[3])
        : "r"(a[0]), "r"(a[1]), "r"(a[2]), "r"(a[3]), "r"(b[0]), "r"(b[1]));
}
__device__ __forceinline__ uint32_t packh(float a, float b) {
    __half2 h = __floats2half2_rn(a, b);
    return *(uint32_t*)&h;
}

// ============================ fused prep (MMA-based) ============================
#define PROWB 144
#define PSXL 18432
#define PSWH 36864
#define PSWL 46080
#define PREP_SMEM 55296

__global__ void __launch_bounds__(256, 1) prep_mma(const float* __restrict__ x,
                                                   const float* __restrict__ W,
                                                   const float* __restrict__ bias) {
    extern __shared__ char smem[];
    uint32_t sb = smem_u32(smem);
    int tid = threadIdx.x;
    int w = tid >> 5, l = tid & 31;
    int bh = blockIdx.x >> 4;
    int s0 = (blockIdx.x & 15) * 128;
    int b = bh >> 4, h = bh & 15;

    #pragma unroll
    for (int t = 0; t < 16; t++) {
        int idx = t * 256 + tid;
        int i = idx >> 6, j = idx & 63;
        float v = W[idx];
        __half hi = __float2half_rn(v);
        *(__half*)(smem + PSWH + j * PROWB + i * 2) = hi;
        *(__half*)(smem + PSWL + j * PROWB + i * 2) = __float2half_rn(v - __half2float(hi));
    }

    #pragma unroll
    for (int t = 0; t < 8; t++) {
        int idx = t * 256 + tid;
        int row = idx >> 4, q = idx & 15;
        float4 v = *(const float4*)(x + (size_t)(b * S_ + s0 + row) * D_ + h * 64 + q * 4);
        __half h0 = __float2half_rn(v.x), h1 = __float2half_rn(v.y);
        __half h2 = __float2half_rn(v.z), h3 = __float2half_rn(v.w);
        uint2 hiw = make_uint2(packh(v.x, v.y), packh(v.z, v.w));
        uint2 low = make_uint2(packh(v.x - __half2float(h0), v.y - __half2float(h1)),
                               packh(v.z - __half2float(h2), v.w - __half2float(h3)));
        *(uint2*)(smem + row * PROWB + q * 8) = hiw;
        *(uint2*)(smem + PSXL + row * PROWB + q * 8) = low;
    }
    __syncthreads();

    #pragma unroll
    for (int t = 0; t < 4; t++) {
        int u = t * 256 + tid;
        int c = (u >> 4) & 63;
        int g8 = u & 15;
        uint32_t base = (uint32_t)c * 2;
        uint32_t pk[4];
        #pragma unroll
        for (int p = 0; p < 4; p++) {
            uint16_t a0 = *(const uint16_t*)(smem + base + (g8 * 8 + 2 * p) * PROWB);
            uint16_t a1 = *(const uint16_t*)(smem + base + (g8 * 8 + 2 * p + 1) * PROWB);
            pk[p] = (uint32_t)a0 | ((uint32_t)a1 << 16);
        }
        __half* dst = g_XhiT + ((size_t)bh * 64 + c) * S_ + s0 + g8 * 8;
        *(uint4*)dst = *(uint4*)pk;
    }

    uint32_t ahi[4][4], alo[4][4];
    #pragma unroll
    for (int j = 0; j < 4; j++) {
        uint32_t ad = sb + (uint32_t)(w * 16 + (l & 15)) * PROWB +
                      (uint32_t)(((l >> 4) * 8 + 16 * j) * 2);
        LDSM_X4(ahi[j][0], ahi[j][1], ahi[j][2], ahi[j][3], ad);
        LDSM_X4(alo[j][0], alo[j][1], alo[j][2], alo[j][3], ad + PSXL);
    }

    int R0 = w * 16 + (l >> 2);
    #pragma unroll
    for (int t2 = 0; t2 < 8; t2++) {
        uint32_t b0 = sb + PSWH + (uint32_t)(t2 * 8 + (l & 7)) * PROWB +
                      (uint32_t)(((l >> 3) * 8) * 2);
        uint32_t bh0, bh1, bh2, bh3, bh4, bh5, bh6, bh7;
        uint32_t bl0, bl1, bl2, bl3, bl4, bl5, bl6, bl7;
        LDSM_X4(bh0, bh1, bh2, bh3, b0);
        LDSM_X4(bh4, bh5, bh6, bh7, b0 + 64u);
        LDSM_X4(bl0, bl1, bl2, bl3, b0 + (PSWL - PSWH));
        LDSM_X4(bl4, bl5, bl6, bl7, b0 + (PSWL - PSWH) + 64u);
        uint32_t bhv[8] = {bh0, bh1, bh2, bh3, bh4, bh5, bh6, bh7};
        uint32_t blv[8] = {bl0, bl1, bl2, bl3, bl4, bl5, bl6, bl7};

        float yA[4] = {0, 0, 0, 0}, yB[4] = {0, 0, 0, 0}, yC[4] = {0, 0, 0, 0};
        #pragma unroll
        for (int j = 0; j < 4; j++) {
            mma16816(yA, ahi[j], &bhv[2 * j]);
            mma16816(yB, alo[j], &bhv[2 * j]);
            mma16816(yC, ahi[j], &blv[2 * j]);
        }
        float y[4];
        #pragma unroll
        for (int q = 0; q < 4; q++) y[q] = yA[q] + yB[q] + yC[q];

        int c = t2 * 8 + (l & 3) * 2;
        float b0f = bias[c], b1f = bias[c + 1];
        y[0] += b0f; y[1] += b1f; y[2] += b0f; y[3] += b1f;

        __half h0 = __float2half_rn(y[0]), h1 = __float2half_rn(y[1]);
        __half h2 = __float2half_rn(y[2]), h3 = __float2half_rn(y[3]);
        size_t o0 = ((size_t)bh * S_ + s0 + R0) * 64 + c;
        size_t o1 = ((size_t)bh * S_ + s0 + R0 + 8) * 64 + c;
        *(uint32_t*)(g_Yhi + o0) = packh(y[0], y[1]);
        *(uint32_t*)(g_Yhi + o1) = packh(y[2], y[3]);
        *(uint32_t*)(g_Ylo + o0) = packh(y[0] - __half2float(h0), y[1] - __half2float(h1));
        *(uint32_t*)(g_Ylo + o1) = packh(y[2] - __half2float(h2), y[3] - __half2float(h3));
    }
}

// ============================ attention kernel ============================
// Back to 256-thread CTA / 128-row q-tiles (round-6 shape, the best performer).
// Change vs round 6: score accumulation split into 3 independent MMA chains
// (depth 4 instead of 12) to remove serial HMMA latency stalls.
#define STG 27648
#define ROWB 144

__device__ __forceinline__ void load_stage(uint32_t base, int bh, int kt, int tid) {
    #pragma unroll
    for (int t = 0; t < 6; t++) {
        int tile = t >> 1;                      // 0: Yhi, 1: Ylo, 2: XhiT
        int idx  = ((t & 1) << 8) + tid;        // 0..511
        int n = idx >> 3, o = idx & 7;
        uint32_t dst = base + (uint32_t)tile * 9216u + (uint32_t)n * ROWB + (uint32_t)o * 16u;
        const __half* src;
        if (tile == 0)      src = g_Yhi  + ((size_t)bh * S_ + kt * 64 + n) * 64 + o * 8;
        else if (tile == 1) src = g_Ylo  + ((size_t)bh * S_ + kt * 64 + n) * 64 + o * 8;
        else                src = g_XhiT + ((size_t)bh * 64 + n) * S_ + kt * 64 + o * 8;
        CP_ASYNC16(dst, src);
    }
    CP_COMMIT();
}

__global__ void __launch_bounds__(256, 1) attn_mma(const int* __restrict__ mask,
                                                   float* __restrict__ out) {
    extern __shared__ char smem[];
    uint32_t sb = smem_u32(smem);
    int tid = threadIdx.x;
    int w = tid >> 5, l = tid & 31;
    int bh = blockIdx.y, b = bh >> 4;
    int q0 = blockIdx.x * 128;

    // ---- Yq (hi/lo) into [0, 36864) via cp.async ----
    #pragma unroll
    for (int t = 0; t < 8; t++) {
        int sel = t >> 2;
        int ii  = ((t & 3) << 8) + tid;
        int row = ii >> 3, o = ii & 7;
        uint32_t dst = sb + (uint32_t)sel * 18432u + (uint32_t)row * ROWB + (uint32_t)o * 16u;
        const __half* src = (sel ? g_Ylo : g_Yhi) + ((size_t)bh * S_ + q0 + row) * 64 + o * 8;
        CP_ASYNC16(dst, src);
    }
    CP_COMMIT();
    CP_WAIT0();
    __syncthreads();

    // ---- extract Yq A-fragments ----
    uint32_t ahi[4][4], alo[4][4];
    #pragma unroll
    for (int j = 0; j < 4; j++) {
        uint32_t ad = sb + (uint32_t)(w * 16 + (l & 15)) * ROWB +
                      (uint32_t)(((l >> 4) * 8 + 16 * j) * 2);
        LDSM_X4(ahi[j][0], ahi[j][1], ahi[j][2], ahi[j][3], ad);
        LDSM_X4(alo[j][0], alo[j][1], alo[j][2], alo[j][3], ad + 18432u);
    }
    __syncthreads();

    // ---- prefetch ktile 0 into stage1 ----
    load_stage(sb + STG, bh, 0, tid);
    CP_WAIT0();
    __syncthreads();

    int R0 = q0 + w * 16 + (l >> 2);
    float negv0 = (1.0f - (float)mask[(size_t)b * S_ + R0]) * NEGV;
    float negv1 = (1.0f - (float)mask[(size_t)b * S_ + R0 + 8]) * NEGV;

    float pv[8][4];
    #pragma unroll
    for (int t = 0; t < 8; t++)
        #pragma unroll
        for (int q = 0; q < 4; q++) pv[t][q] = 0.0f;
    float l0 = 0.0f, l1 = 0.0f;

    uint32_t pAhi[4][4];

    for (int kt = 0; kt < 32; kt++) {
        uint32_t cur = sb + (uint32_t)((kt + 1) & 1) * STG;
        if (kt < 31) load_stage(sb + (uint32_t)(kt & 1) * STG, bh, kt + 1, tid);

        // ---- scores: 3 independent accumulation chains (depth 4 each) ----
        #pragma unroll
        for (int t = 0; t < 8; t++) {
            uint32_t b0 = cur + (uint32_t)(t * 8 + (l & 7)) * ROWB + (uint32_t)(((l >> 3) * 8) * 2);
            uint32_t bh0, bh1, bh2, bh3, bh4, bh5, bh6, bh7;
            uint32_t bl0, bl1, bl2, bl3, bl4, bl5, bl6, bl7;
            LDSM_X4(bh0, bh1, bh2, bh3, b0);
            LDSM_X4(bh4, bh5, bh6, bh7, b0 + 64u);
            LDSM_X4(bl0, bl1, bl2, bl3, b0 + 9216u);
            LDSM_X4(bl4, bl5, bl6, bl7, b0 + 9216u + 64u);
            uint32_t bhv[8] = {bh0, bh1, bh2, bh3, bh4, bh5, bh6, bh7};
            uint32_t blv[8] = {bl0, bl1, bl2, bl3, bl4, bl5, bl6, bl7};

            float sA[4] = {0, 0, 0, 0}, sB[4] = {0, 0, 0, 0}, sC[4] = {0, 0, 0, 0};
            #pragma unroll
            for (int j = 0; j < 4; j++) {
                mma16816(sA, ahi[j], &bhv[2 * j]);
                mma16816(sB, alo[j], &bhv[2 * j]);
                mma16816(sC, ahi[j], &blv[2 * j]);
            }
            float s[4];
            #pragma unroll
            for (int q = 0; q < 4; q++) s[q] = sA[q] + sB[q] + sC[q];

            float lg0 = __fadd_rn(__fmul_rn(s[0], 0.015625f), negv0);
            float lg1 = __fadd_rn(__fmul_rn(s[1], 0.015625f), negv0);
            float lg2 = __fadd_rn(__fmul_rn(s[2], 0.015625f), negv1);
            float lg3 = __fadd_rn(__fmul_rn(s[3], 0.015625f), negv1);
            float p0 = __expf(lg0 - negv0);
            float p1 = __expf(lg1 - negv0);
            float p2 = __expf(lg2 - negv1);
            float p3 = __expf(lg3 - negv1);
            l0 += p0 + p1;
            l1 += p2 + p3;

            pAhi[t >> 1][(t & 1) * 2 + 0] = packh(p0, p1);
            pAhi[t >> 1][(t & 1) * 2 + 1] = packh(p2, p3);
        }

        // ---- PV (1-term): pv += P_hi . X_hi  (8 independent chains) ----
        #pragma unroll
        for (int t2 = 0; t2 < 8; t2++) {
            uint32_t b0 = cur + 18432u + (uint32_t)(t2 * 8 + (l & 7)) * ROWB +
                          (uint32_t)(((l >> 3) * 8) * 2);
            uint32_t bh0, bh1, bh2, bh3, bh4, bh5, bh6, bh7;
            LDSM_X4(bh0, bh1, bh2, bh3, b0);
            LDSM_X4(bh4, bh5, bh6, bh7, b0 + 64u);
            uint32_t bhv[8] = {bh0, bh1, bh2, bh3, bh4, bh5, bh6, bh7};
            #pragma unroll
            for (int j = 0; j < 4; j++)
                mma16816(pv[t2], pAhi[j], &bhv[2 * j]);
        }

        CP_WAIT0();
        __syncthreads();
    }

    // ---- epilogue ----
    l0 += __shfl_xor_sync(0xffffffffu, l0, 1);
    l0 += __shfl_xor_sync(0xffffffffu, l0, 2);
    l1 += __shfl_xor_sync(0xffffffffu, l1, 1);
    l1 += __shfl_xor_sync(0xffffffffu, l1, 2);
    float i0 = 1.0f / l0, i1 = 1.0f / l1;

    #pragma unroll
    for (int t2 = 0; t2 < 8; t2++) {
        int c = t2 * 8 + (l & 3) * 2;
        float2 v0 = make_float2(pv[t2][0] * i0, pv[t2][1] * i0);
        float2 v1 = make_float2(pv[t2][2] * i1, pv[t2][3] * i1);
        *(float2*)(out + ((size_t)bh * S_ + R0) * 64 + c)     = v0;
        *(float2*)(out + ((size_t)bh * S_ + R0 + 8) * 64 + c) = v1;
    }
}

// ============================ launch ============================
extern "C" void kernel_launch(void* const* d_in, const int* in_sizes, int n_in,
                              void* d_out, int out_size) {
    const float* x    = (const float*)d_in[0];
    const int*   mask = (const int*)d_in[1];
    const float* W    = (const float*)d_in[2];
    const float* bias = (const float*)d_in[3];
    float* out = (float*)d_out;

    cudaFuncSetAttribute(prep_mma, cudaFuncAttributeMaxDynamicSharedMemorySize, PREP_SMEM);
    prep_mma<<<BH * 16, 256, PREP_SMEM>>>(x, W, bias);

    cudaFuncSetAttribute(attn_mma, cudaFuncAttributeMaxDynamicSharedMemorySize, 2 * STG);
    dim3 grid(S_ / 128, BH);
    attn_mma<<<grid, 256, 2 * STG>>>(mask, out);
}

// round 9
// speedup vs baseline: 1.1418x; 1.0999x over previous
#include <cuda_runtime.h>
#include <cuda_fp16.h>
#include <cstdint>
#include <math.h>

#define B_ 4
#define H_ 16
#define S_ 2048
#define D_ 1024
#define BH 64
#define dh 64
#define NEGV (-1000000.0f)

// ============================ device scratch ============================
__device__ __half g_Yhi[(size_t)BH * S_ * dh];
__device__ __half g_Ylo[(size_t)BH * S_ * dh];
__device__ __half g_XhiT[(size_t)BH * dh * S_];   // [bh][c][s]

// ============================ PTX helpers ============================
__device__ __forceinline__ uint32_t smem_u32(const void* p) {
    uint32_t a;
    asm("{ .reg .u64 t; cvta.to.shared.u64 t, %1; cvt.u32.u64 %0, t; }" : "=r"(a) : "l"(p));
    return a;
}
#define LDSM_X4(r0, r1, r2, r3, addr) \
    asm volatile("ldmatrix.sync.aligned.m8n8.x4.shared.b16 {%0,%1,%2,%3}, [%4];" \
        : "=r"(r0), "=r"(r1), "=r"(r2), "=r"(r3) : "r"(addr))
#define CP_ASYNC16(dst, src) \
    asm volatile("cp.async.cg.shared.global [%0], [%1], 16;" :: "r"(dst), "l"(src))
#define CP_COMMIT() asm volatile("cp.async.commit_group;")
#define CP_WAIT0()  asm volatile("cp.async.wait_group 0;")

__device__ __forceinline__ void mma16816(float d[4], const uint32_t a[4], const uint32_t b[2]) {
    asm volatile(
        "mma.sync.aligned.m16n8k16.row.col.f32.f16.f16.f32 "
        "{%0,%1,%2,%3}, {%4,%5,%6,%7}, {%8,%9}, {%0,%1,%2,%3};"
        : "+f"(d[0]), "+f"(d[1]), "+f"(d[2]), "+f"(d[3])
        : "r"(a[0]), "r"(a[1]), "r"(a[2]), "r"(a[3]), "r"(b[0]), "r"(b[1]));
}
__device__ __forceinline__ uint32_t packh(float a, float b) {
    __half2 h = __floats2half2_rn(a, b);
    return *(uint32_t*)&h;
}

// ============================ fused prep (MMA-based, round-6 form) ============================
#define PROWB 144
#define PSXL 18432
#define PSWH 36864
#define PSWL 46080
#define PREP_SMEM 55296

__global__ void __launch_bounds__(256, 1) prep_mma(const float* __restrict__ x,
                                                   const float* __restrict__ W,
                                                   const float* __restrict__ bias) {
    extern __shared__ char smem[];
    uint32_t sb = smem_u32(smem);
    int tid = threadIdx.x;
    int w = tid >> 5, l = tid & 31;
    int bh = blockIdx.x >> 4;
    int s0 = (blockIdx.x & 15) * 128;
    int b = bh >> 4, h = bh & 15;

    #pragma unroll
    for (int t = 0; t < 16; t++) {
        int idx = t * 256 + tid;
        int i = idx >> 6, j = idx & 63;
        float v = W[idx];
        __half hi = __float2half_rn(v);
        *(__half*)(smem + PSWH + j * PROWB + i * 2) = hi;
        *(__half*)(smem + PSWL + j * PROWB + i * 2) = __float2half_rn(v - __half2float(hi));
    }

    #pragma unroll
    for (int t = 0; t < 8; t++) {
        int idx = t * 256 + tid;
        int row = idx >> 4, q = idx & 15;
        float4 v = *(const float4*)(x + (size_t)(b * S_ + s0 + row) * D_ + h * 64 + q * 4);
        __half h0 = __float2half_rn(v.x), h1 = __float2half_rn(v.y);
        __half h2 = __float2half_rn(v.z), h3 = __float2half_rn(v.w);
        uint2 hiw = make_uint2(packh(v.x, v.y), packh(v.z, v.w));
        uint2 low = make_uint2(packh(v.x - __half2float(h0), v.y - __half2float(h1)),
                               packh(v.z - __half2float(h2), v.w - __half2float(h3)));
        *(uint2*)(smem + row * PROWB + q * 8) = hiw;
        *(uint2*)(smem + PSXL + row * PROWB + q * 8) = low;
    }
    __syncthreads();

    #pragma unroll
    for (int t = 0; t < 4; t++) {
        int u = t * 256 + tid;
        int c = (u >> 4) & 63;
        int g8 = u & 15;
        uint32_t base = (uint32_t)c * 2;
        uint32_t pk[4];
        #pragma unroll
        for (int p = 0; p < 4; p++) {
            uint16_t a0 = *(const uint16_t*)(smem + base + (g8 * 8 + 2 * p) * PROWB);
            uint16_t a1 = *(const uint16_t*)(smem + base + (g8 * 8 + 2 * p + 1) * PROWB);
            pk[p] = (uint32_t)a0 | ((uint32_t)a1 << 16);
        }
        __half* dst = g_XhiT + ((size_t)bh * 64 + c) * S_ + s0 + g8 * 8;
        *(uint4*)dst = *(uint4*)pk;
    }

    uint32_t ahi[4][4], alo[4][4];
    #pragma unroll
    for (int j = 0; j < 4; j++) {
        uint32_t ad = sb + (uint32_t)(w * 16 + (l & 15)) * PROWB +
                      (uint32_t)(((l >> 4) * 8 + 16 * j) * 2);
        LDSM_X4(ahi[j][0], ahi[j][1], ahi[j][2], ahi[j][3], ad);
        LDSM_X4(alo[j][0], alo[j][1], alo[j][2], alo[j][3], ad + PSXL);
    }

    int R0 = w * 16 + (l >> 2);
    #pragma unroll
    for (int t2 = 0; t2 < 8; t2++) {
        uint32_t b0 = sb + PSWH + (uint32_t)(t2 * 8 + (l & 7)) * PROWB +
                      (uint32_t)(((l >> 3) * 8) * 2);
        uint32_t bh0, bh1, bh2, bh3, bh4, bh5, bh6, bh7;
        uint32_t bl0, bl1, bl2, bl3, bl4, bl5, bl6, bl7;
        LDSM_X4(bh0, bh1, bh2, bh3, b0);
        LDSM_X4(bh4, bh5, bh6, bh7, b0 + 64u);
        LDSM_X4(bl0, bl1, bl2, bl3, b0 + (PSWL - PSWH));
        LDSM_X4(bl4, bl5, bl6, bl7, b0 + (PSWL - PSWH) + 64u);
        uint32_t bhv[8] = {bh0, bh1, bh2, bh3, bh4, bh5, bh6, bh7};
        uint32_t blv[8] = {bl0, bl1, bl2, bl3, bl4, bl5, bl6, bl7};

        float y[4] = {0.0f, 0.0f, 0.0f, 0.0f};
        #pragma unroll
        for (int j = 0; j < 4; j++) {
            mma16816(y, ahi[j], &bhv[2 * j]);
            mma16816(y, alo[j], &bhv[2 * j]);
            mma16816(y, ahi[j], &blv[2 * j]);
        }

        int c = t2 * 8 + (l & 3) * 2;
        float b0f = bias[c], b1f = bias[c + 1];
        y[0] += b0f; y[1] += b1f; y[2] += b0f; y[3] += b1f;

        __half h0 = __float2half_rn(y[0]), h1 = __float2half_rn(y[1]);
        __half h2 = __float2half_rn(y[2]), h3 = __float2half_rn(y[3]);
        size_t o0 = ((size_t)bh * S_ + s0 + R0) * 64 + c;
        size_t o1 = ((size_t)bh * S_ + s0 + R0 + 8) * 64 + c;
        *(uint32_t*)(g_Yhi + o0) = packh(y[0], y[1]);
        *(uint32_t*)(g_Yhi + o1) = packh(y[2], y[3]);
        *(uint32_t*)(g_Ylo + o0) = packh(y[0] - __half2float(h0), y[1] - __half2float(h1));
        *(uint32_t*)(g_Ylo + o1) = packh(y[2] - __half2float(h2), y[3] - __half2float(h3));
    }
}

// ============================ attention kernel ============================
// Round-6 shape (256 threads / 128-row q-tiles, single-chain accumulators).
// NEW: each ktile split into two 32-key halves; PV of half h follows scores of
// half h, so PV HMMAs overlap the other half's softmax/MUFU. Numerics identical.
#define STG 27648
#define ROWB 144

__device__ __forceinline__ void load_stage(uint32_t base, int bh, int kt, int tid) {
    #pragma unroll
    for (int t = 0; t < 6; t++) {
        int tile = t >> 1;                      // 0: Yhi, 1: Ylo, 2: XhiT
        int idx  = ((t & 1) << 8) + tid;        // 0..511
        int n = idx >> 3, o = idx & 7;
        uint32_t dst = base + (uint32_t)tile * 9216u + (uint32_t)n * ROWB + (uint32_t)o * 16u;
        const __half* src;
        if (tile == 0)      src = g_Yhi  + ((size_t)bh * S_ + kt * 64 + n) * 64 + o * 8;
        else if (tile == 1) src = g_Ylo  + ((size_t)bh * S_ + kt * 64 + n) * 64 + o * 8;
        else                src = g_XhiT + ((size_t)bh * 64 + n) * S_ + kt * 64 + o * 8;
        CP_ASYNC16(dst, src);
    }
    CP_COMMIT();
}

__global__ void __launch_bounds__(256, 1) attn_mma(const int* __restrict__ mask,
                                                   float* __restrict__ out) {
    extern __shared__ char smem[];
    uint32_t sb = smem_u32(smem);
    int tid = threadIdx.x;
    int w = tid >> 5, l = tid & 31;
    int bh = blockIdx.y, b = bh >> 4;
    int q0 = blockIdx.x * 128;

    // ---- Yq (hi/lo) into [0, 36864) via cp.async ----
    #pragma unroll
    for (int t = 0; t < 8; t++) {
        int sel = t >> 2;
        int ii  = ((t & 3) << 8) + tid;
        int row = ii >> 3, o = ii & 7;
        uint32_t dst = sb + (uint32_t)sel * 18432u + (uint32_t)row * ROWB + (uint32_t)o * 16u;
        const __half* src = (sel ? g_Ylo : g_Yhi) + ((size_t)bh * S_ + q0 + row) * 64 + o * 8;
        CP_ASYNC16(dst, src);
    }
    CP_COMMIT();
    CP_WAIT0();
    __syncthreads();

    // ---- extract Yq A-fragments ----
    uint32_t ahi[4][4], alo[4][4];
    #pragma unroll
    for (int j = 0; j < 4; j++) {
        uint32_t ad = sb + (uint32_t)(w * 16 + (l & 15)) * ROWB +
                      (uint32_t)(((l >> 4) * 8 + 16 * j) * 2);
        LDSM_X4(ahi[j][0], ahi[j][1], ahi[j][2], ahi[j][3], ad);
        LDSM_X4(alo[j][0], alo[j][1], alo[j][2], alo[j][3], ad + 18432u);
    }
    __syncthreads();

    // ---- prefetch ktile 0 into stage1 ----
    load_stage(sb + STG, bh, 0, tid);
    CP_WAIT0();
    __syncthreads();

    int R0 = q0 + w * 16 + (l >> 2);
    float negv0 = (1.0f - (float)mask[(size_t)b * S_ + R0]) * NEGV;
    float negv1 = (1.0f - (float)mask[(size_t)b * S_ + R0 + 8]) * NEGV;

    float pv[8][4];
    #pragma unroll
    for (int t = 0; t < 8; t++)
        #pragma unroll
        for (int q = 0; q < 4; q++) pv[t][q] = 0.0f;
    float l0 = 0.0f, l1 = 0.0f;

    for (int kt = 0; kt < 32; kt++) {
        uint32_t cur = sb + (uint32_t)((kt + 1) & 1) * STG;
        if (kt < 31) load_stage(sb + (uint32_t)(kt & 1) * STG, bh, kt + 1, tid);

        #pragma unroll
        for (int half = 0; half < 2; half++) {
            uint32_t pA[2][4];   // P for this half's 32 keys

            // ---- scores (3-term, single chain) + softmax + pack ----
            #pragma unroll
            for (int tt = 0; tt < 4; tt++) {
                int t = half * 4 + tt;
                uint32_t b0 = cur + (uint32_t)(t * 8 + (l & 7)) * ROWB +
                              (uint32_t)(((l >> 3) * 8) * 2);
                uint32_t bh0, bh1, bh2, bh3, bh4, bh5, bh6, bh7;
                uint32_t bl0, bl1, bl2, bl3, bl4, bl5, bl6, bl7;
                LDSM_X4(bh0, bh1, bh2, bh3, b0);
                LDSM_X4(bh4, bh5, bh6, bh7, b0 + 64u);
                LDSM_X4(bl0, bl1, bl2, bl3, b0 + 9216u);
                LDSM_X4(bl4, bl5, bl6, bl7, b0 + 9216u + 64u);
                uint32_t bhv[8] = {bh0, bh1, bh2, bh3, bh4, bh5, bh6, bh7};
                uint32_t blv[8] = {bl0, bl1, bl2, bl3, bl4, bl5, bl6, bl7};

                float s[4] = {0.0f, 0.0f, 0.0f, 0.0f};
                #pragma unroll
                for (int j = 0; j < 4; j++) {
                    mma16816(s, ahi[j], &bhv[2 * j]);
                    mma16816(s, alo[j], &bhv[2 * j]);
                    mma16816(s, ahi[j], &blv[2 * j]);
                }

                float lg0 = __fadd_rn(__fmul_rn(s[0], 0.015625f), negv0);
                float lg1 = __fadd_rn(__fmul_rn(s[1], 0.015625f), negv0);
                float lg2 = __fadd_rn(__fmul_rn(s[2], 0.015625f), negv1);
                float lg3 = __fadd_rn(__fmul_rn(s[3], 0.015625f), negv1);
                float p0 = __expf(lg0 - negv0);
                float p1 = __expf(lg1 - negv0);
                float p2 = __expf(lg2 - negv1);
                float p3 = __expf(lg3 - negv1);
                l0 += p0 + p1;
                l1 += p2 + p3;

                pA[tt >> 1][(tt & 1) * 2 + 0] = packh(p0, p1);
                pA[tt >> 1][(tt & 1) * 2 + 1] = packh(p2, p3);
            }

            // ---- PV for this half's 32 keys (k offset: half*32 halves = 64B) ----
            #pragma unroll
            for (int t2 = 0; t2 < 8; t2++) {
                uint32_t b0 = cur + 18432u + (uint32_t)(t2 * 8 + (l & 7)) * ROWB +
                              (uint32_t)(((l >> 3) * 8) * 2) + (uint32_t)half * 64u;
                uint32_t bh0, bh1, bh2, bh3;
                LDSM_X4(bh0, bh1, bh2, bh3, b0);
                uint32_t bhv[4] = {bh0, bh1, bh2, bh3};
                mma16816(pv[t2], pA[0], &bhv[0]);
                mma16816(pv[t2], pA[1], &bhv[2]);
            }
        }

        CP_WAIT0();
        __syncthreads();
    }

    // ---- epilogue ----
    l0 += __shfl_xor_sync(0xffffffffu, l0, 1);
    l0 += __shfl_xor_sync(0xffffffffu, l0, 2);
    l1 += __shfl_xor_sync(0xffffffffu, l1, 1);
    l1 += __shfl_xor_sync(0xffffffffu, l1, 2);
    float i0 = 1.0f / l0, i1 = 1.0f / l1;

    #pragma unroll
    for (int t2 = 0; t2 < 8; t2++) {
        int c = t2 * 8 + (l & 3) * 2;
        float2 v0 = make_float2(pv[t2][0] * i0, pv[t2][1] * i0);
        float2 v1 = make_float2(pv[t2][2] * i1, pv[t2][3] * i1);
        *(float2*)(out + ((size_t)bh * S_ + R0) * 64 + c)     = v0;
        *(float2*)(out + ((size_t)bh * S_ + R0 + 8) * 64 + c) = v1;
    }
}

// ============================ launch ============================
extern "C" void kernel_launch(void* const* d_in, const int* in_sizes, int n_in,
                              void* d_out, int out_size) {
    const float* x    = (const float*)d_in[0];
    const int*   mask = (const int*)d_in[1];
    const float* W    = (const float*)d_in[2];
    const float* bias = (const float*)d_in[3];
    float* out = (float*)d_out;

    cudaFuncSetAttribute(prep_mma, cudaFuncAttributeMaxDynamicSharedMemorySize, PREP_SMEM);
    prep_mma<<<BH * 16, 256, PREP_SMEM>>>(x, W, bias);

    cudaFuncSetAttribute(attn_mma, cudaFuncAttributeMaxDynamicSharedMemorySize, 2 * STG);
    dim3 grid(S_ / 128, BH);
    attn_mma<<<grid, 256, 2 * STG>>>(mask, out);
}